// round 3
// baseline (speedup 1.0000x reference)
#include <cuda_runtime.h>
#include <cuda_bf16.h>
#include <math_constants.h>

#define BB 512
#define QQ 100
#define CC 81
#define VV 117
#define NQ (BB*QQ)

// Output layout (flattened tuple, float32):
// hoi_scores [B,Q,V] | obj_labels [B,Q] | sub_boxes [B,Q,4] | obj_boxes [B,Q,4] | keep [B,Q]
#define OFF_HOI  0ull
#define OFF_LAB  ((unsigned long long)NQ * VV)
#define OFF_SUB  (OFF_LAB + (unsigned long long)NQ)
#define OFF_OBJ  (OFF_SUB + (unsigned long long)NQ * 4)
#define OFF_KEEP (OFF_OBJ + (unsigned long long)NQ * 4)

__device__ __forceinline__ float pair_iou(float ax1, float ay1, float ax2, float ay2, float aA,
                                          float bx1, float by1, float bx2, float by2, float bA)
{
    float xx1 = fmaxf(ax1, bx1), yy1 = fmaxf(ay1, by1);
    float xx2 = fminf(ax2, bx2), yy2 = fminf(ay2, by2);
    float w = fmaxf(0.0f, xx2 - xx1 + 1.0f);
    float h = fmaxf(0.0f, yy2 - yy1 + 1.0f);
    float inter = w * h;
    return inter / (aA + bA - inter);
}

// ---------------------------------------------------------------------------
// Fused kernel: one block (512 threads = 16 warps) per image.
// Stage A: warp-per-query scoring + boxes (results cached in shared).
// Stage B: in-block NMS with ballot-built suppression bitmasks.
// ---------------------------------------------------------------------------
__global__ __launch_bounds__(512)
void k_fused(const float* __restrict__ obj_logits,
             const float* __restrict__ verb_logits,
             const float* __restrict__ sub_in,
             const float* __restrict__ obj_in,
             const float* __restrict__ cmat,     // [V, C]
             const int* __restrict__ ts,         // [B, 2] (h, w) int32
             float* __restrict__ out)
{
    const int b    = blockIdx.x;
    const int tid  = threadIdx.x;
    const int wid  = tid >> 5;
    const int lane = tid & 31;

    __shared__ float s_max[QQ];          // per-query max hoi score
    __shared__ int   s_lab[QQ];          // per-query label (original order)
    __shared__ float s_sb[QQ][4];        // scaled xyxy sub boxes (original order)
    __shared__ float s_ob[QQ][4];        // scaled xyxy obj boxes
    __shared__ int   s_orig[QQ];         // sorted rank -> original index
    __shared__ int   r_lab[QQ];          // label in sorted order
    __shared__ float r_s[5][QQ];         // sorted sub: x1,y1,x2,y2,area
    __shared__ float r_o[5][QQ];         // sorted obj: x1,y1,x2,y2,area
    __shared__ unsigned supmat[QQ][4];
    __shared__ unsigned suppw[4];

    const float img_h = (float)ts[b * 2 + 0];
    const float img_w = (float)ts[b * 2 + 1];

    // ============================ Stage A ================================
    for (int q = wid; q < QQ; q += 16) {
        const int gq = b * QQ + q;

        // softmax over 81 logits; max/argmax over first 80
        const float* ol = obj_logits + (size_t)gq * CC;
        float l0 = ol[lane];
        float l1 = (lane + 32 < CC) ? ol[lane + 32] : -CUDART_INF_F;
        float l2 = (lane + 64 < CC) ? ol[lane + 64] : -CUDART_INF_F;

        float m = fmaxf(l0, fmaxf(l1, l2));
        #pragma unroll
        for (int o = 16; o; o >>= 1) m = fmaxf(m, __shfl_xor_sync(0xffffffffu, m, o));

        float s = expf(l0 - m);
        if (lane + 32 < CC) s += expf(l1 - m);
        if (lane + 64 < CC) s += expf(l2 - m);
        #pragma unroll
        for (int o = 16; o; o >>= 1) s += __shfl_xor_sync(0xffffffffu, s, o);

        float bv = l0; int bi = lane;
        if (lane + 32 < CC - 1 && l1 > bv) { bv = l1; bi = lane + 32; }
        if (lane + 64 < CC - 1 && l2 > bv) { bv = l2; bi = lane + 64; }
        #pragma unroll
        for (int o = 16; o; o >>= 1) {
            float ov = __shfl_xor_sync(0xffffffffu, bv, o);
            int   oi = __shfl_xor_sync(0xffffffffu, bi, o);
            if (ov > bv || (ov == bv && oi < bi)) { bv = ov; bi = oi; }
        }
        const float obj_score = expf(bv - m) / s;
        const int   label = bi;

        // hoi scores
        const float* vl = verb_logits + (size_t)gq * VV;
        float* ho = out + OFF_HOI + (size_t)gq * VV;
        float mx = -CUDART_INF_F;
        #pragma unroll
        for (int v = lane; v < VV; v += 32) {
            float sig = 1.0f / (1.0f + expf(-vl[v]));
            float h = sig * obj_score * cmat[(size_t)v * CC + label];
            ho[v] = h;
            mx = fmaxf(mx, h);
        }
        #pragma unroll
        for (int o = 16; o; o >>= 1) mx = fmaxf(mx, __shfl_xor_sync(0xffffffffu, mx, o));

        if (lane == 0) {
            s_max[q] = mx;
            s_lab[q] = label;
            out[OFF_LAB + gq] = (float)label;
        }

        // boxes: cxcywh -> xyxy, scaled
        if (lane < 8) {
            const int kk = lane & 3;
            const float* bx = ((lane < 4) ? sub_in : obj_in) + (size_t)gq * 4;
            float c = bx[kk & 1];
            float d = bx[(kk & 1) + 2];
            float sc = (kk & 1) ? img_h : img_w;
            float val = ((kk < 2) ? (c - 0.5f * d) : (c + 0.5f * d)) * sc;
            if (lane < 4) s_sb[q][kk] = val; else s_ob[q][kk] = val;
            out[((lane < 4) ? OFF_SUB : OFF_OBJ) + (size_t)gq * 4 + kk] = val;
        }
    }
    __syncthreads();

    // ============================ Stage B ================================
    // stable descending rank (matches jnp.argsort(-scores))
    if (tid < QQ) {
        float mine = s_max[tid];
        int r = 0;
        #pragma unroll 4
        for (int j = 0; j < QQ; j++) {
            float o = s_max[j];
            r += (o > mine) || (o == mine && j < tid);
        }
        float a1 = s_sb[tid][0], a2 = s_sb[tid][1], a3 = s_sb[tid][2], a4 = s_sb[tid][3];
        r_s[0][r] = a1; r_s[1][r] = a2; r_s[2][r] = a3; r_s[3][r] = a4;
        r_s[4][r] = (a3 - a1 + 1.0f) * (a4 - a2 + 1.0f);
        float c1 = s_ob[tid][0], c2 = s_ob[tid][1], c3 = s_ob[tid][2], c4 = s_ob[tid][3];
        r_o[0][r] = c1; r_o[1][r] = c2; r_o[2][r] = c3; r_o[3][r] = c4;
        r_o[4][r] = (c3 - c1 + 1.0f) * (c4 - c2 + 1.0f);
        r_lab[r]  = s_lab[tid];
        s_orig[r] = tid;
    }
    __syncthreads();

    // Each lane owns 4 fixed columns; load their sorted boxes into registers.
    float jsx1[4], jsy1[4], jsx2[4], jsy2[4], jsA[4];
    float jox1[4], joy1[4], jox2[4], joy2[4], joA[4];
    int   jlab[4], jidx[4];
    #pragma unroll
    for (int k = 0; k < 4; k++) {
        int j = lane + 32 * k;
        jidx[k] = j;
        if (j < QQ) {
            jsx1[k] = r_s[0][j]; jsy1[k] = r_s[1][j]; jsx2[k] = r_s[2][j];
            jsy2[k] = r_s[3][j]; jsA[k]  = r_s[4][j];
            jox1[k] = r_o[0][j]; joy1[k] = r_o[1][j]; jox2[k] = r_o[2][j];
            joy2[k] = r_o[3][j]; joA[k]  = r_o[4][j];
            jlab[k] = r_lab[j];
        } else {
            jsx1[k]=jsy1[k]=jsx2[k]=jsy2[k]=jsA[k]=0.f;
            jox1[k]=joy1[k]=jox2[k]=joy2[k]=joA[k]=0.f;
            jlab[k] = -1;
        }
    }

    // Build suppression matrix row-by-row with ballots (no atomics).
    for (int i = wid; i < QQ; i += 16) {
        float ix1 = r_s[0][i], iy1 = r_s[1][i], ix2 = r_s[2][i], iy2 = r_s[3][i], iA = r_s[4][i];
        float px1 = r_o[0][i], py1 = r_o[1][i], px2 = r_o[2][i], py2 = r_o[3][i], pA = r_o[4][i];
        int   il  = r_lab[i];
        unsigned words[4];
        #pragma unroll
        for (int k = 0; k < 4; k++) {
            bool pred = false;
            if (jidx[k] > i && jlab[k] == il) {
                float iou_s = pair_iou(ix1, iy1, ix2, iy2, iA,
                                       jsx1[k], jsy1[k], jsx2[k], jsy2[k], jsA[k]);
                float iou_o = pair_iou(px1, py1, px2, py2, pA,
                                       jox1[k], joy1[k], jox2[k], joy2[k], joA[k]);
                pred = (iou_s * sqrtf(iou_o)) > 0.7f;   // ALPHA=1, BETA=0.5, THRES
            }
            words[k] = __ballot_sync(0xffffffffu, pred);
        }
        if (lane == 0) {
            supmat[i][0] = words[0]; supmat[i][1] = words[1];
            supmat[i][2] = words[2]; supmat[i][3] = words[3];
        }
    }
    __syncthreads();

    // sequential greedy suppression, bit-parallel across 4 words
    if (tid == 0) {
        unsigned w0 = 0, w1 = 0, w2 = 0, w3 = 0;
        #pragma unroll 4
        for (int i = 0; i < QQ; i++) {
            unsigned wi = (i < 32) ? w0 : (i < 64) ? w1 : (i < 96) ? w2 : w3;
            if (!((wi >> (i & 31)) & 1u)) {
                w0 |= supmat[i][0];
                w1 |= supmat[i][1];
                w2 |= supmat[i][2];
                w3 |= supmat[i][3];
            }
        }
        suppw[0] = w0; suppw[1] = w1; suppw[2] = w2; suppw[3] = w3;
    }
    __syncthreads();

    if (tid < QQ) {
        bool suppressed = (suppw[tid >> 5] >> (tid & 31)) & 1u;
        out[OFF_KEEP + b * QQ + s_orig[tid]] = suppressed ? 0.0f : 1.0f;
    }
}

// ---------------------------------------------------------------------------
extern "C" void kernel_launch(void* const* d_in, const int* in_sizes, int n_in,
                              void* d_out, int out_size)
{
    const float* obj_logits  = (const float*)d_in[0];
    const float* verb_logits = (const float*)d_in[1];
    const float* sub_boxes   = (const float*)d_in[2];
    const float* obj_boxes   = (const float*)d_in[3];
    const float* correct_mat = (const float*)d_in[4];
    const int*   target_sz   = (const int*)d_in[5];
    float* out = (float*)d_out;

    k_fused<<<BB, 512>>>(obj_logits, verb_logits, sub_boxes, obj_boxes,
                         correct_mat, target_sz, out);
}

// round 4
// speedup vs baseline: 2.1822x; 2.1822x over previous
#include <cuda_runtime.h>
#include <cuda_bf16.h>
#include <math_constants.h>

#define BB 512
#define QQ 100
#define CC 81
#define VV 117
#define NQ (BB*QQ)

// Output layout (flattened tuple, float32):
// hoi_scores [B,Q,V] | obj_labels [B,Q] | sub_boxes [B,Q,4] | obj_boxes [B,Q,4] | keep [B,Q]
#define OFF_HOI  0ull
#define OFF_LAB  ((unsigned long long)NQ * VV)
#define OFF_SUB  (OFF_LAB + (unsigned long long)NQ)
#define OFF_OBJ  (OFF_SUB + (unsigned long long)NQ * 4)
#define OFF_KEEP (OFF_OBJ + (unsigned long long)NQ * 4)

// Scratch: per-query max hoi score for NMS
__device__ float g_maxsc[NQ];

// ---------------------------------------------------------------------------
// Kernel 1: per-query scoring + boxes. One warp per query, 4 warps per block.
// Fast-math intrinsics (__expf / __fdividef): rel err ~1e-6, tolerance 1e-3.
// ---------------------------------------------------------------------------
__global__ __launch_bounds__(128)
void k1_score(const float* __restrict__ obj_logits,
              const float* __restrict__ verb_logits,
              const float* __restrict__ sub_in,
              const float* __restrict__ obj_in,
              const float* __restrict__ cmat,     // [V, C]
              const int* __restrict__ ts,         // [B, 2] (h, w) int32
              float* __restrict__ out)
{
    const int warp = threadIdx.x >> 5;
    const int lane = threadIdx.x & 31;
    const int gq = blockIdx.x * 4 + warp;
    if (gq >= NQ) return;
    const int b = gq / QQ;

    // ---- softmax over 81 obj logits; max/argmax over first 80 ----
    const float* ol = obj_logits + (size_t)gq * CC;
    float l0 = ol[lane];
    float l1 = (lane + 32 < CC) ? ol[lane + 32] : -CUDART_INF_F;
    float l2 = (lane + 64 < CC) ? ol[lane + 64] : -CUDART_INF_F;

    float m = fmaxf(l0, fmaxf(l1, l2));
    #pragma unroll
    for (int o = 16; o; o >>= 1) m = fmaxf(m, __shfl_xor_sync(0xffffffffu, m, o));

    float s = __expf(l0 - m);
    if (lane + 32 < CC) s += __expf(l1 - m);
    if (lane + 64 < CC) s += __expf(l2 - m);
    #pragma unroll
    for (int o = 16; o; o >>= 1) s += __shfl_xor_sync(0xffffffffu, s, o);

    // argmax over classes [0, 80)
    float bv = l0; int bi = lane;
    if (lane + 32 < CC - 1 && l1 > bv) { bv = l1; bi = lane + 32; }
    if (lane + 64 < CC - 1 && l2 > bv) { bv = l2; bi = lane + 64; }
    #pragma unroll
    for (int o = 16; o; o >>= 1) {
        float ov = __shfl_xor_sync(0xffffffffu, bv, o);
        int   oi = __shfl_xor_sync(0xffffffffu, bi, o);
        if (ov > bv || (ov == bv && oi < bi)) { bv = ov; bi = oi; }
    }
    const float obj_score = __fdividef(__expf(bv - m), s);
    const int   label = bi;

    // ---- hoi scores = sigmoid(verb) * obj_score * correct_mat[v, label] ----
    const float* vl = verb_logits + (size_t)gq * VV;
    float* ho = out + OFF_HOI + (size_t)gq * VV;
    float mx = -CUDART_INF_F;
    #pragma unroll
    for (int v = lane; v < VV; v += 32) {
        float e = __expf(-vl[v]);
        float sig = __fdividef(1.0f, 1.0f + e);
        float h = sig * obj_score * cmat[(size_t)v * CC + label];
        ho[v] = h;
        mx = fmaxf(mx, h);
    }
    #pragma unroll
    for (int o = 16; o; o >>= 1) mx = fmaxf(mx, __shfl_xor_sync(0xffffffffu, mx, o));

    if (lane == 0) {
        g_maxsc[gq] = mx;
        out[OFF_LAB + gq] = (float)label;
    }

    // ---- boxes: cxcywh -> xyxy, * [w,h,w,h] ----
    if (lane < 8) {
        const int kk = lane & 3;
        const float* bx = ((lane < 4) ? sub_in : obj_in) + (size_t)gq * 4;
        float c = bx[kk & 1];
        float d = bx[(kk & 1) + 2];
        float sc = (kk & 1) ? (float)ts[b * 2 + 0] : (float)ts[b * 2 + 1];
        float val = ((kk < 2) ? (c - 0.5f * d) : (c + 0.5f * d)) * sc;
        out[((lane < 4) ? OFF_SUB : OFF_OBJ) + (size_t)gq * 4 + kk] = val;
    }
}

// ---------------------------------------------------------------------------
// Kernel 2: per-image NMS, one block (128 threads = 4 warps) per image.
// Ballot-built suppression bitmasks: no atomics, no integer division.
// ---------------------------------------------------------------------------
__device__ __forceinline__ float pair_iou(float ax1, float ay1, float ax2, float ay2, float aA,
                                          float bx1, float by1, float bx2, float by2, float bA)
{
    float xx1 = fmaxf(ax1, bx1), yy1 = fmaxf(ay1, by1);
    float xx2 = fminf(ax2, bx2), yy2 = fminf(ay2, by2);
    float w = fmaxf(0.0f, xx2 - xx1 + 1.0f);
    float h = fmaxf(0.0f, yy2 - yy1 + 1.0f);
    float inter = w * h;
    return inter / (aA + bA - inter);
}

__global__ __launch_bounds__(128)
void k2_nms(float* __restrict__ out)
{
    const int b    = blockIdx.x;
    const int tid  = threadIdx.x;
    const int wid  = tid >> 5;
    const int lane = tid & 31;

    __shared__ float sc[QQ];
    __shared__ int   s_orig[QQ];
    __shared__ int   r_lab[QQ];
    __shared__ float r_s[5][QQ];   // sorted sub boxes: x1,y1,x2,y2,area
    __shared__ float r_o[5][QQ];   // sorted obj boxes
    __shared__ unsigned supmat[QQ][4];
    __shared__ unsigned suppw[4];

    if (tid < QQ) sc[tid] = g_maxsc[b * QQ + tid];
    __syncthreads();

    if (tid < QQ) {
        // stable descending rank (matches jnp.argsort(-scores), stable)
        float mine = sc[tid];
        int r = 0;
        #pragma unroll 4
        for (int j = 0; j < QQ; j++) {
            float o = sc[j];
            r += (o > mine) || (o == mine && j < tid);
        }
        const size_t base = (size_t)(b * QQ + tid);
        float4 sb = *(const float4*)(out + OFF_SUB + base * 4);
        float4 ob = *(const float4*)(out + OFF_OBJ + base * 4);
        r_s[0][r] = sb.x; r_s[1][r] = sb.y; r_s[2][r] = sb.z; r_s[3][r] = sb.w;
        r_s[4][r] = (sb.z - sb.x + 1.0f) * (sb.w - sb.y + 1.0f);
        r_o[0][r] = ob.x; r_o[1][r] = ob.y; r_o[2][r] = ob.z; r_o[3][r] = ob.w;
        r_o[4][r] = (ob.z - ob.x + 1.0f) * (ob.w - ob.y + 1.0f);
        r_lab[r]  = (int)out[OFF_LAB + base];
        s_orig[r] = tid;
    }
    __syncthreads();

    // Each lane owns 4 fixed columns j = lane + 32k; boxes in registers.
    float jsx1[4], jsy1[4], jsx2[4], jsy2[4], jsA[4];
    float jox1[4], joy1[4], jox2[4], joy2[4], joA[4];
    int   jlab[4];
    #pragma unroll
    for (int k = 0; k < 4; k++) {
        int j = lane + 32 * k;
        if (j < QQ) {
            jsx1[k] = r_s[0][j]; jsy1[k] = r_s[1][j]; jsx2[k] = r_s[2][j];
            jsy2[k] = r_s[3][j]; jsA[k]  = r_s[4][j];
            jox1[k] = r_o[0][j]; joy1[k] = r_o[1][j]; jox2[k] = r_o[2][j];
            joy2[k] = r_o[3][j]; joA[k]  = r_o[4][j];
            jlab[k] = r_lab[j];
        } else {
            jsx1[k]=jsy1[k]=jsx2[k]=jsy2[k]=jsA[k]=0.f;
            jox1[k]=joy1[k]=jox2[k]=joy2[k]=joA[k]=0.f;
            jlab[k] = -1;
        }
    }

    // Build suppression rows with ballots (warp-uniform row index).
    for (int i = wid; i < QQ; i += 4) {
        float ix1 = r_s[0][i], iy1 = r_s[1][i], ix2 = r_s[2][i], iy2 = r_s[3][i], iA = r_s[4][i];
        float px1 = r_o[0][i], py1 = r_o[1][i], px2 = r_o[2][i], py2 = r_o[3][i], pA = r_o[4][i];
        int   il  = r_lab[i];
        unsigned words[4];
        #pragma unroll
        for (int k = 0; k < 4; k++) {
            int j = lane + 32 * k;
            bool pred = false;
            if (j > i && jlab[k] == il) {
                float iou_s = pair_iou(ix1, iy1, ix2, iy2, iA,
                                       jsx1[k], jsy1[k], jsx2[k], jsy2[k], jsA[k]);
                float iou_o = pair_iou(px1, py1, px2, py2, pA,
                                       jox1[k], joy1[k], jox2[k], joy2[k], joA[k]);
                pred = (iou_s * sqrtf(iou_o)) > 0.7f;    // ALPHA=1, BETA=0.5
            }
            words[k] = __ballot_sync(0xffffffffu, pred);
        }
        if (lane == 0) {
            supmat[i][0] = words[0]; supmat[i][1] = words[1];
            supmat[i][2] = words[2]; supmat[i][3] = words[3];
        }
    }
    __syncthreads();

    // sequential greedy suppression, bit-parallel across 4 words
    if (tid == 0) {
        unsigned w0 = 0, w1 = 0, w2 = 0, w3 = 0;
        #pragma unroll 4
        for (int i = 0; i < QQ; i++) {
            unsigned wi = (i < 32) ? w0 : (i < 64) ? w1 : (i < 96) ? w2 : w3;
            if (!((wi >> (i & 31)) & 1u)) {
                w0 |= supmat[i][0];
                w1 |= supmat[i][1];
                w2 |= supmat[i][2];
                w3 |= supmat[i][3];
            }
        }
        suppw[0] = w0; suppw[1] = w1; suppw[2] = w2; suppw[3] = w3;
    }
    __syncthreads();

    if (tid < QQ) {
        bool suppressed = (suppw[tid >> 5] >> (tid & 31)) & 1u;
        out[OFF_KEEP + b * QQ + s_orig[tid]] = suppressed ? 0.0f : 1.0f;
    }
}

// ---------------------------------------------------------------------------
extern "C" void kernel_launch(void* const* d_in, const int* in_sizes, int n_in,
                              void* d_out, int out_size)
{
    const float* obj_logits  = (const float*)d_in[0];
    const float* verb_logits = (const float*)d_in[1];
    const float* sub_boxes   = (const float*)d_in[2];
    const float* obj_boxes   = (const float*)d_in[3];
    const float* correct_mat = (const float*)d_in[4];
    const int*   target_sz   = (const int*)d_in[5];
    float* out = (float*)d_out;

    k1_score<<<NQ / 4, 128>>>(obj_logits, verb_logits, sub_boxes, obj_boxes,
                              correct_mat, target_sz, out);
    k2_nms<<<BB, 128>>>(out);
}

// round 5
// speedup vs baseline: 2.2864x; 1.0477x over previous
#include <cuda_runtime.h>
#include <cuda_bf16.h>
#include <math_constants.h>

#define BB 512
#define QQ 100
#define CC 81
#define VV 117
#define NQ (BB*QQ)

// Output layout (flattened tuple, float32):
// hoi_scores [B,Q,V] | obj_labels [B,Q] | sub_boxes [B,Q,4] | obj_boxes [B,Q,4] | keep [B,Q]
#define OFF_HOI  0ull
#define OFF_LAB  ((unsigned long long)NQ * VV)
#define OFF_SUB  (OFF_LAB + (unsigned long long)NQ)
#define OFF_OBJ  (OFF_SUB + (unsigned long long)NQ * 4)
#define OFF_KEEP (OFF_OBJ + (unsigned long long)NQ * 4)

// Scratch: per-query max hoi score for NMS
__device__ float g_maxsc[NQ];

// ---------------------------------------------------------------------------
// Kernel 1: per-query scoring + boxes. One warp per query, 4 warps per block.
// ---------------------------------------------------------------------------
__global__ __launch_bounds__(128)
void k1_score(const float* __restrict__ obj_logits,
              const float* __restrict__ verb_logits,
              const float* __restrict__ sub_in,
              const float* __restrict__ obj_in,
              const float* __restrict__ cmat,     // [V, C]
              const int* __restrict__ ts,         // [B, 2] (h, w) int32
              float* __restrict__ out)
{
    const int warp = threadIdx.x >> 5;
    const int lane = threadIdx.x & 31;
    const int gq = blockIdx.x * 4 + warp;
    if (gq >= NQ) return;
    const int b = gq / QQ;

    // ---- softmax over 81 obj logits; max/argmax over first 80 ----
    const float* ol = obj_logits + (size_t)gq * CC;
    float l0 = ol[lane];
    float l1 = (lane + 32 < CC) ? ol[lane + 32] : -CUDART_INF_F;
    float l2 = (lane + 64 < CC) ? ol[lane + 64] : -CUDART_INF_F;

    float m = fmaxf(l0, fmaxf(l1, l2));
    #pragma unroll
    for (int o = 16; o; o >>= 1) m = fmaxf(m, __shfl_xor_sync(0xffffffffu, m, o));

    float s = __expf(l0 - m);
    if (lane + 32 < CC) s += __expf(l1 - m);
    if (lane + 64 < CC) s += __expf(l2 - m);
    #pragma unroll
    for (int o = 16; o; o >>= 1) s += __shfl_xor_sync(0xffffffffu, s, o);

    // argmax over classes [0, 80)
    float bv = l0; int bi = lane;
    if (lane + 32 < CC - 1 && l1 > bv) { bv = l1; bi = lane + 32; }
    if (lane + 64 < CC - 1 && l2 > bv) { bv = l2; bi = lane + 64; }
    #pragma unroll
    for (int o = 16; o; o >>= 1) {
        float ov = __shfl_xor_sync(0xffffffffu, bv, o);
        int   oi = __shfl_xor_sync(0xffffffffu, bi, o);
        if (ov > bv || (ov == bv && oi < bi)) { bv = ov; bi = oi; }
    }
    const float obj_score = __fdividef(__expf(bv - m), s);
    const int   label = bi;

    // ---- hoi scores = sigmoid(verb) * obj_score * correct_mat[v, label] ----
    const float* vl = verb_logits + (size_t)gq * VV;
    float* ho = out + OFF_HOI + (size_t)gq * VV;
    float mx = -CUDART_INF_F;
    #pragma unroll
    for (int v = lane; v < VV; v += 32) {
        float e = __expf(-vl[v]);
        float sig = __fdividef(1.0f, 1.0f + e);
        float h = sig * obj_score * cmat[(size_t)v * CC + label];
        ho[v] = h;
        mx = fmaxf(mx, h);
    }
    #pragma unroll
    for (int o = 16; o; o >>= 1) mx = fmaxf(mx, __shfl_xor_sync(0xffffffffu, mx, o));

    if (lane == 0) {
        g_maxsc[gq] = mx;
        out[OFF_LAB + gq] = (float)label;
    }

    // ---- boxes: cxcywh -> xyxy, * [w,h,w,h] ----
    if (lane < 8) {
        const int kk = lane & 3;
        const float* bx = ((lane < 4) ? sub_in : obj_in) + (size_t)gq * 4;
        float c = bx[kk & 1];
        float d = bx[(kk & 1) + 2];
        float sc = (kk & 1) ? (float)ts[b * 2 + 0] : (float)ts[b * 2 + 1];
        float val = ((kk < 2) ? (c - 0.5f * d) : (c + 0.5f * d)) * sc;
        out[((lane < 4) ? OFF_SUB : OFF_OBJ) + (size_t)gq * 4 + kk] = val;
    }
}

// ---------------------------------------------------------------------------
// Kernel 2: per-image NMS, one block (256 threads = 8 warps) per image.
// Division/sqrt-free threshold test:
//   (is/us) * sqrt(io/uo) > 0.7  <=>  is*is*io > 0.49 * us*us*uo
// (all intersections >= 0, unions > 0 since box widths/heights are positive)
// ---------------------------------------------------------------------------
__global__ __launch_bounds__(256)
void k2_nms(float* __restrict__ out)
{
    const int b    = blockIdx.x;
    const int tid  = threadIdx.x;
    const int wid  = tid >> 5;
    const int lane = tid & 31;

    __shared__ float sc[QQ];
    __shared__ int   s_orig[QQ];
    __shared__ int   r_lab[QQ];
    __shared__ float r_s[5][QQ];   // sorted sub: x1,y1,x2,y2,area
    __shared__ float r_o[5][QQ];   // sorted obj: x1,y1,x2,y2,area
    __shared__ unsigned supmat[QQ][4];
    __shared__ unsigned suppw[4];

    if (tid < QQ) sc[tid] = g_maxsc[b * QQ + tid];
    __syncthreads();

    if (tid < QQ) {
        // stable descending rank (matches jnp.argsort(-scores), stable)
        float mine = sc[tid];
        int r = 0;
        #pragma unroll 4
        for (int j = 0; j < QQ; j++) {
            float o = sc[j];
            r += (o > mine) || (o == mine && j < tid);
        }
        const size_t base = (size_t)(b * QQ + tid);
        float4 sb = *(const float4*)(out + OFF_SUB + base * 4);
        float4 ob = *(const float4*)(out + OFF_OBJ + base * 4);
        r_s[0][r] = sb.x; r_s[1][r] = sb.y; r_s[2][r] = sb.z; r_s[3][r] = sb.w;
        r_s[4][r] = (sb.z - sb.x + 1.0f) * (sb.w - sb.y + 1.0f);
        r_o[0][r] = ob.x; r_o[1][r] = ob.y; r_o[2][r] = ob.z; r_o[3][r] = ob.w;
        r_o[4][r] = (ob.z - ob.x + 1.0f) * (ob.w - ob.y + 1.0f);
        r_lab[r]  = (int)out[OFF_LAB + base];
        s_orig[r] = tid;
    }
    __syncthreads();

    // Each lane owns 4 fixed columns j = lane + 32k; boxes in registers.
    float jsx1[4], jsy1[4], jsx2[4], jsy2[4], jsA[4];
    float jox1[4], joy1[4], jox2[4], joy2[4], joA[4];
    int   jlab[4];
    #pragma unroll
    for (int k = 0; k < 4; k++) {
        int j = lane + 32 * k;
        if (j < QQ) {
            jsx1[k] = r_s[0][j]; jsy1[k] = r_s[1][j]; jsx2[k] = r_s[2][j];
            jsy2[k] = r_s[3][j]; jsA[k]  = r_s[4][j];
            jox1[k] = r_o[0][j]; joy1[k] = r_o[1][j]; jox2[k] = r_o[2][j];
            joy2[k] = r_o[3][j]; joA[k]  = r_o[4][j];
            jlab[k] = r_lab[j];
        } else {
            jsx1[k]=jsy1[k]=jsx2[k]=jsy2[k]=jsA[k]=0.f;
            jox1[k]=joy1[k]=jox2[k]=joy2[k]=joA[k]=0.f;
            jlab[k] = -1;
        }
    }

    // Build suppression rows with ballots; 8 warps stride rows.
    for (int i = wid; i < QQ; i += 8) {
        float ix1 = r_s[0][i], iy1 = r_s[1][i], ix2 = r_s[2][i], iy2 = r_s[3][i], iA = r_s[4][i];
        float px1 = r_o[0][i], py1 = r_o[1][i], px2 = r_o[2][i], py2 = r_o[3][i], pA = r_o[4][i];
        int   il  = r_lab[i];
        unsigned words[4];
        #pragma unroll
        for (int k = 0; k < 4; k++) {
            int j = lane + 32 * k;
            bool pred = false;
            if (j > i && jlab[k] == il) {
                // sub IoU terms
                float w = fmaxf(0.0f, fminf(ix2, jsx2[k]) - fmaxf(ix1, jsx1[k]) + 1.0f);
                float h = fmaxf(0.0f, fminf(iy2, jsy2[k]) - fmaxf(iy1, jsy1[k]) + 1.0f);
                float is = w * h;
                float us = iA + jsA[k] - is;
                // obj IoU terms
                float w2 = fmaxf(0.0f, fminf(px2, jox2[k]) - fmaxf(px1, jox1[k]) + 1.0f);
                float h2 = fmaxf(0.0f, fminf(py2, joy2[k]) - fmaxf(py1, joy1[k]) + 1.0f);
                float io = w2 * h2;
                float uo = pA + joA[k] - io;
                // (is/us)*sqrt(io/uo) > 0.7  <=>  is^2*io > 0.49*us^2*uo
                pred = (is * is) * io > 0.49f * (us * us) * uo;
            }
            words[k] = __ballot_sync(0xffffffffu, pred);
        }
        if (lane == 0) {
            supmat[i][0] = words[0]; supmat[i][1] = words[1];
            supmat[i][2] = words[2]; supmat[i][3] = words[3];
        }
    }
    __syncthreads();

    // sequential greedy suppression, bit-parallel across 4 words
    if (tid == 0) {
        unsigned w0 = 0, w1 = 0, w2 = 0, w3 = 0;
        #pragma unroll 4
        for (int i = 0; i < QQ; i++) {
            unsigned wi = (i < 32) ? w0 : (i < 64) ? w1 : (i < 96) ? w2 : w3;
            if (!((wi >> (i & 31)) & 1u)) {
                w0 |= supmat[i][0];
                w1 |= supmat[i][1];
                w2 |= supmat[i][2];
                w3 |= supmat[i][3];
            }
        }
        suppw[0] = w0; suppw[1] = w1; suppw[2] = w2; suppw[3] = w3;
    }
    __syncthreads();

    if (tid < QQ) {
        bool suppressed = (suppw[tid >> 5] >> (tid & 31)) & 1u;
        out[OFF_KEEP + b * QQ + s_orig[tid]] = suppressed ? 0.0f : 1.0f;
    }
}

// ---------------------------------------------------------------------------
extern "C" void kernel_launch(void* const* d_in, const int* in_sizes, int n_in,
                              void* d_out, int out_size)
{
    const float* obj_logits  = (const float*)d_in[0];
    const float* verb_logits = (const float*)d_in[1];
    const float* sub_boxes   = (const float*)d_in[2];
    const float* obj_boxes   = (const float*)d_in[3];
    const float* correct_mat = (const float*)d_in[4];
    const int*   target_sz   = (const int*)d_in[5];
    float* out = (float*)d_out;

    k1_score<<<NQ / 4, 128>>>(obj_logits, verb_logits, sub_boxes, obj_boxes,
                              correct_mat, target_sz, out);
    k2_nms<<<BB, 256>>>(out);
}

// round 6
// speedup vs baseline: 2.6787x; 1.1716x over previous
#include <cuda_runtime.h>
#include <cuda_bf16.h>
#include <math_constants.h>

#define BB 512
#define QQ 100
#define CC 81
#define VV 117
#define NQ (BB*QQ)

// Output layout (flattened tuple, float32):
// hoi_scores [B,Q,V] | obj_labels [B,Q] | sub_boxes [B,Q,4] | obj_boxes [B,Q,4] | keep [B,Q]
#define OFF_HOI  0ull
#define OFF_LAB  ((unsigned long long)NQ * VV)
#define OFF_SUB  (OFF_LAB + (unsigned long long)NQ)
#define OFF_OBJ  (OFF_SUB + (unsigned long long)NQ * 4)
#define OFF_KEEP (OFF_OBJ + (unsigned long long)NQ * 4)

// Scratch: per-query max hoi score for NMS
__device__ float g_maxsc[NQ];

// ---------------------------------------------------------------------------
// Kernel 1: per-query scoring + boxes. One warp per query, 8 warps per block.
// ---------------------------------------------------------------------------
__global__ __launch_bounds__(256)
void k1_score(const float* __restrict__ obj_logits,
              const float* __restrict__ verb_logits,
              const float* __restrict__ sub_in,
              const float* __restrict__ obj_in,
              const float* __restrict__ cmat,     // [V, C]
              const int* __restrict__ ts,         // [B, 2] (h, w) int32
              float* __restrict__ out)
{
    const int warp = threadIdx.x >> 5;
    const int lane = threadIdx.x & 31;
    const int gq = blockIdx.x * 8 + warp;
    if (gq >= NQ) return;
    const int b = gq / QQ;

    // ---- softmax over 81 obj logits; max/argmax over first 80 ----
    const float* ol = obj_logits + (size_t)gq * CC;
    float l0 = ol[lane];
    float l1 = (lane + 32 < CC) ? ol[lane + 32] : -CUDART_INF_F;
    float l2 = (lane + 64 < CC) ? ol[lane + 64] : -CUDART_INF_F;

    float m = fmaxf(l0, fmaxf(l1, l2));
    #pragma unroll
    for (int o = 16; o; o >>= 1) m = fmaxf(m, __shfl_xor_sync(0xffffffffu, m, o));

    float s = __expf(l0 - m);
    if (lane + 32 < CC) s += __expf(l1 - m);
    if (lane + 64 < CC) s += __expf(l2 - m);
    #pragma unroll
    for (int o = 16; o; o >>= 1) s += __shfl_xor_sync(0xffffffffu, s, o);

    // argmax over classes [0, 80)
    float bv = l0; int bi = lane;
    if (lane + 32 < CC - 1 && l1 > bv) { bv = l1; bi = lane + 32; }
    if (lane + 64 < CC - 1 && l2 > bv) { bv = l2; bi = lane + 64; }
    #pragma unroll
    for (int o = 16; o; o >>= 1) {
        float ov = __shfl_xor_sync(0xffffffffu, bv, o);
        int   oi = __shfl_xor_sync(0xffffffffu, bi, o);
        if (ov > bv || (ov == bv && oi < bi)) { bv = ov; bi = oi; }
    }
    const float obj_score = __fdividef(__expf(bv - m), s);
    const int   label = bi;

    // ---- hoi scores = sigmoid(verb) * obj_score * correct_mat[v, label] ----
    const float* vl = verb_logits + (size_t)gq * VV;
    float* ho = out + OFF_HOI + (size_t)gq * VV;
    float mx = -CUDART_INF_F;
    #pragma unroll
    for (int v = lane; v < VV; v += 32) {
        float e = __expf(-vl[v]);
        float sig = __fdividef(1.0f, 1.0f + e);
        float h = sig * obj_score * cmat[(size_t)v * CC + label];
        ho[v] = h;
        mx = fmaxf(mx, h);
    }
    #pragma unroll
    for (int o = 16; o; o >>= 1) mx = fmaxf(mx, __shfl_xor_sync(0xffffffffu, mx, o));

    if (lane == 0) {
        g_maxsc[gq] = mx;
        out[OFF_LAB + gq] = (float)label;
    }

    // ---- boxes: cxcywh -> xyxy, * [w,h,w,h] ----
    if (lane < 8) {
        const int kk = lane & 3;
        const float* bx = ((lane < 4) ? sub_in : obj_in) + (size_t)gq * 4;
        float c = bx[kk & 1];
        float d = bx[(kk & 1) + 2];
        float sc = (kk & 1) ? (float)ts[b * 2 + 0] : (float)ts[b * 2 + 1];
        float val = ((kk < 2) ? (c - 0.5f * d) : (c + 0.5f * d)) * sc;
        out[((lane < 4) ? OFF_SUB : OFF_OBJ) + (size_t)gq * 4 + kk] = val;
    }
}

// ---------------------------------------------------------------------------
// Kernel 2: per-image NMS, one block (256 threads = 8 warps) per image.
// __launch_bounds__(256, 4): cap regs at 64 so 4 blocks/SM -> single wave.
// Division/sqrt-free test: (is/us)*sqrt(io/uo) > 0.7 <=> is^2*io > 0.49*us^2*uo
// ---------------------------------------------------------------------------
__global__ __launch_bounds__(256, 4)
void k2_nms(float* __restrict__ out)
{
    const int b    = blockIdx.x;
    const int tid  = threadIdx.x;
    const int wid  = tid >> 5;
    const int lane = tid & 31;

    __shared__ float sc[QQ];
    __shared__ int   s_orig[QQ];
    __shared__ int   r_lab[QQ];
    __shared__ float r_s[5][QQ];   // sorted sub: x1,y1,x2,y2,area
    __shared__ float r_o[5][QQ];   // sorted obj: x1,y1,x2,y2,area
    __shared__ unsigned supmat[QQ][4];
    __shared__ unsigned suppw[4];

    if (tid < QQ) sc[tid] = g_maxsc[b * QQ + tid];
    __syncthreads();

    if (tid < QQ) {
        // stable descending rank (matches jnp.argsort(-scores), stable)
        float mine = sc[tid];
        int r = 0;
        #pragma unroll 4
        for (int j = 0; j < QQ; j++) {
            float o = sc[j];
            r += (o > mine) || (o == mine && j < tid);
        }
        const size_t base = (size_t)(b * QQ + tid);
        float4 sb = *(const float4*)(out + OFF_SUB + base * 4);
        float4 ob = *(const float4*)(out + OFF_OBJ + base * 4);
        r_s[0][r] = sb.x; r_s[1][r] = sb.y; r_s[2][r] = sb.z; r_s[3][r] = sb.w;
        r_s[4][r] = (sb.z - sb.x + 1.0f) * (sb.w - sb.y + 1.0f);
        r_o[0][r] = ob.x; r_o[1][r] = ob.y; r_o[2][r] = ob.z; r_o[3][r] = ob.w;
        r_o[4][r] = (ob.z - ob.x + 1.0f) * (ob.w - ob.y + 1.0f);
        r_lab[r]  = (int)out[OFF_LAB + base];
        s_orig[r] = tid;
    }
    __syncthreads();

    // Each lane owns 4 fixed columns j = lane + 32k; boxes in registers.
    float jsx1[4], jsy1[4], jsx2[4], jsy2[4], jsA[4];
    float jox1[4], joy1[4], jox2[4], joy2[4], joA[4];
    int   jlab[4];
    #pragma unroll
    for (int k = 0; k < 4; k++) {
        int j = lane + 32 * k;
        if (j < QQ) {
            jsx1[k] = r_s[0][j]; jsy1[k] = r_s[1][j]; jsx2[k] = r_s[2][j];
            jsy2[k] = r_s[3][j]; jsA[k]  = r_s[4][j];
            jox1[k] = r_o[0][j]; joy1[k] = r_o[1][j]; jox2[k] = r_o[2][j];
            joy2[k] = r_o[3][j]; joA[k]  = r_o[4][j];
            jlab[k] = r_lab[j];
        } else {
            jsx1[k]=jsy1[k]=jsx2[k]=jsy2[k]=jsA[k]=0.f;
            jox1[k]=joy1[k]=jox2[k]=joy2[k]=joA[k]=0.f;
            jlab[k] = -1;
        }
    }

    // Build suppression rows with ballots; 8 warps stride rows.
    for (int i = wid; i < QQ; i += 8) {
        float ix1 = r_s[0][i], iy1 = r_s[1][i], ix2 = r_s[2][i], iy2 = r_s[3][i], iA = r_s[4][i];
        float px1 = r_o[0][i], py1 = r_o[1][i], px2 = r_o[2][i], py2 = r_o[3][i], pA = r_o[4][i];
        int   il  = r_lab[i];
        unsigned words[4];
        #pragma unroll
        for (int k = 0; k < 4; k++) {
            int j = lane + 32 * k;
            bool pred = false;
            if (j > i && jlab[k] == il) {
                float w = fmaxf(0.0f, fminf(ix2, jsx2[k]) - fmaxf(ix1, jsx1[k]) + 1.0f);
                float h = fmaxf(0.0f, fminf(iy2, jsy2[k]) - fmaxf(iy1, jsy1[k]) + 1.0f);
                float is = w * h;
                float us = iA + jsA[k] - is;
                float w2 = fmaxf(0.0f, fminf(px2, jox2[k]) - fmaxf(px1, jox1[k]) + 1.0f);
                float h2 = fmaxf(0.0f, fminf(py2, joy2[k]) - fmaxf(py1, joy1[k]) + 1.0f);
                float io = w2 * h2;
                float uo = pA + joA[k] - io;
                pred = (is * is) * io > 0.49f * (us * us) * uo;
            }
            words[k] = __ballot_sync(0xffffffffu, pred);
        }
        if (lane == 0) {
            supmat[i][0] = words[0]; supmat[i][1] = words[1];
            supmat[i][2] = words[2]; supmat[i][3] = words[3];
        }
    }
    __syncthreads();

    // sequential greedy suppression, bit-parallel across 4 words
    if (tid == 0) {
        unsigned w0 = 0, w1 = 0, w2 = 0, w3 = 0;
        #pragma unroll 4
        for (int i = 0; i < QQ; i++) {
            unsigned wi = (i < 32) ? w0 : (i < 64) ? w1 : (i < 96) ? w2 : w3;
            if (!((wi >> (i & 31)) & 1u)) {
                w0 |= supmat[i][0];
                w1 |= supmat[i][1];
                w2 |= supmat[i][2];
                w3 |= supmat[i][3];
            }
        }
        suppw[0] = w0; suppw[1] = w1; suppw[2] = w2; suppw[3] = w3;
    }
    __syncthreads();

    if (tid < QQ) {
        bool suppressed = (suppw[tid >> 5] >> (tid & 31)) & 1u;
        out[OFF_KEEP + b * QQ + s_orig[tid]] = suppressed ? 0.0f : 1.0f;
    }
}

// ---------------------------------------------------------------------------
extern "C" void kernel_launch(void* const* d_in, const int* in_sizes, int n_in,
                              void* d_out, int out_size)
{
    const float* obj_logits  = (const float*)d_in[0];
    const float* verb_logits = (const float*)d_in[1];
    const float* sub_boxes   = (const float*)d_in[2];
    const float* obj_boxes   = (const float*)d_in[3];
    const float* correct_mat = (const float*)d_in[4];
    const int*   target_sz   = (const int*)d_in[5];
    float* out = (float*)d_out;

    k1_score<<<NQ / 8, 256>>>(obj_logits, verb_logits, sub_boxes, obj_boxes,
                              correct_mat, target_sz, out);
    k2_nms<<<BB, 256>>>(out);
}

// round 7
// speedup vs baseline: 2.6991x; 1.0076x over previous
#include <cuda_runtime.h>
#include <cuda_bf16.h>
#include <math_constants.h>

#define BB 512
#define QQ 100
#define CC 81
#define VV 117
#define NQ (BB*QQ)

// Output layout (flattened tuple, float32):
// hoi_scores [B,Q,V] | obj_labels [B,Q] | sub_boxes [B,Q,4] | obj_boxes [B,Q,4] | keep [B,Q]
#define OFF_HOI  0ull
#define OFF_LAB  ((unsigned long long)NQ * VV)
#define OFF_SUB  (OFF_LAB + (unsigned long long)NQ)
#define OFF_OBJ  (OFF_SUB + (unsigned long long)NQ * 4)
#define OFF_KEEP (OFF_OBJ + (unsigned long long)NQ * 4)

// Scratch: per-query max hoi score for NMS
__device__ float g_maxsc[NQ];

// ---------------------------------------------------------------------------
// Kernel 1: per-query scoring + boxes. One warp per query, 8 warps per block.
// ---------------------------------------------------------------------------
__global__ __launch_bounds__(256)
void k1_score(const float* __restrict__ obj_logits,
              const float* __restrict__ verb_logits,
              const float* __restrict__ sub_in,
              const float* __restrict__ obj_in,
              const float* __restrict__ cmat,     // [V, C]
              const int* __restrict__ ts,         // [B, 2] (h, w) int32
              float* __restrict__ out)
{
    const int warp = threadIdx.x >> 5;
    const int lane = threadIdx.x & 31;
    const int gq = blockIdx.x * 8 + warp;
    if (gq >= NQ) return;
    const int b = gq / QQ;

    // ---- softmax over 81 obj logits; max/argmax over first 80 ----
    const float* ol = obj_logits + (size_t)gq * CC;
    float l0 = ol[lane];
    float l1 = (lane + 32 < CC) ? ol[lane + 32] : -CUDART_INF_F;
    float l2 = (lane + 64 < CC) ? ol[lane + 64] : -CUDART_INF_F;

    float m = fmaxf(l0, fmaxf(l1, l2));
    #pragma unroll
    for (int o = 16; o; o >>= 1) m = fmaxf(m, __shfl_xor_sync(0xffffffffu, m, o));

    float s = __expf(l0 - m);
    if (lane + 32 < CC) s += __expf(l1 - m);
    if (lane + 64 < CC) s += __expf(l2 - m);
    #pragma unroll
    for (int o = 16; o; o >>= 1) s += __shfl_xor_sync(0xffffffffu, s, o);

    // argmax over classes [0, 80)
    float bv = l0; int bi = lane;
    if (lane + 32 < CC - 1 && l1 > bv) { bv = l1; bi = lane + 32; }
    if (lane + 64 < CC - 1 && l2 > bv) { bv = l2; bi = lane + 64; }
    #pragma unroll
    for (int o = 16; o; o >>= 1) {
        float ov = __shfl_xor_sync(0xffffffffu, bv, o);
        int   oi = __shfl_xor_sync(0xffffffffu, bi, o);
        if (ov > bv || (ov == bv && oi < bi)) { bv = ov; bi = oi; }
    }
    const float obj_score = __fdividef(__expf(bv - m), s);
    const int   label = bi;

    // ---- hoi scores = sigmoid(verb) * obj_score * correct_mat[v, label] ----
    const float* vl = verb_logits + (size_t)gq * VV;
    float* ho = out + OFF_HOI + (size_t)gq * VV;
    float mx = -CUDART_INF_F;
    #pragma unroll
    for (int v = lane; v < VV; v += 32) {
        float e = __expf(-vl[v]);
        float sig = __fdividef(1.0f, 1.0f + e);
        float h = sig * obj_score * cmat[(size_t)v * CC + label];
        ho[v] = h;
        mx = fmaxf(mx, h);
    }
    #pragma unroll
    for (int o = 16; o; o >>= 1) mx = fmaxf(mx, __shfl_xor_sync(0xffffffffu, mx, o));

    if (lane == 0) {
        g_maxsc[gq] = mx;
        out[OFF_LAB + gq] = (float)label;
    }

    // ---- boxes: cxcywh -> xyxy, * [w,h,w,h] ----
    if (lane < 8) {
        const int kk = lane & 3;
        const float* bx = ((lane < 4) ? sub_in : obj_in) + (size_t)gq * 4;
        float c = bx[kk & 1];
        float d = bx[(kk & 1) + 2];
        float sc = (kk & 1) ? (float)ts[b * 2 + 0] : (float)ts[b * 2 + 1];
        float val = ((kk < 2) ? (c - 0.5f * d) : (c + 0.5f * d)) * sc;
        out[((lane < 4) ? OFF_SUB : OFF_OBJ) + (size_t)gq * 4 + kk] = val;
    }
}

// ---------------------------------------------------------------------------
// Kernel 2: per-image NMS, one block (256 threads = 8 warps) per image.
// Two-level gating: cheap label-match ballot per 32-col word; IoU math only
// when the word is non-zero (~1/3 of words, since P(label match) ~ 1/80).
// Division/sqrt-free test: is^2*io > 0.49*us^2*uo.
// ---------------------------------------------------------------------------
__global__ __launch_bounds__(256, 4)
void k2_nms(float* __restrict__ out)
{
    const int b    = blockIdx.x;
    const int tid  = threadIdx.x;
    const int wid  = tid >> 5;
    const int lane = tid & 31;

    __shared__ float sc[QQ];
    __shared__ int   s_orig[QQ];
    __shared__ int   r_lab[QQ];
    __shared__ float r_s[5][QQ];   // sorted sub: x1,y1,x2,y2,area
    __shared__ float r_o[5][QQ];   // sorted obj: x1,y1,x2,y2,area
    __shared__ uint4 supmat4[QQ];
    __shared__ unsigned suppw[4];

    if (tid < QQ) sc[tid] = g_maxsc[b * QQ + tid];
    __syncthreads();

    if (tid < QQ) {
        // stable descending rank (matches jnp.argsort(-scores), stable)
        float mine = sc[tid];
        int r = 0;
        #pragma unroll 4
        for (int j = 0; j < QQ; j++) {
            float o = sc[j];
            r += (o > mine) || (o == mine && j < tid);
        }
        const size_t base = (size_t)(b * QQ + tid);
        float4 sb = *(const float4*)(out + OFF_SUB + base * 4);
        float4 ob = *(const float4*)(out + OFF_OBJ + base * 4);
        r_s[0][r] = sb.x; r_s[1][r] = sb.y; r_s[2][r] = sb.z; r_s[3][r] = sb.w;
        r_s[4][r] = (sb.z - sb.x + 1.0f) * (sb.w - sb.y + 1.0f);
        r_o[0][r] = ob.x; r_o[1][r] = ob.y; r_o[2][r] = ob.z; r_o[3][r] = ob.w;
        r_o[4][r] = (ob.z - ob.x + 1.0f) * (ob.w - ob.y + 1.0f);
        r_lab[r]  = (int)out[OFF_LAB + base];
        s_orig[r] = tid;
    }
    __syncthreads();

    // Each lane owns 4 fixed columns j = lane + 32k; boxes in registers.
    float jsx1[4], jsy1[4], jsx2[4], jsy2[4], jsA[4];
    float jox1[4], joy1[4], jox2[4], joy2[4], joA[4];
    int   jlab[4];
    #pragma unroll
    for (int k = 0; k < 4; k++) {
        int j = lane + 32 * k;
        if (j < QQ) {
            jsx1[k] = r_s[0][j]; jsy1[k] = r_s[1][j]; jsx2[k] = r_s[2][j];
            jsy2[k] = r_s[3][j]; jsA[k]  = r_s[4][j];
            jox1[k] = r_o[0][j]; joy1[k] = r_o[1][j]; jox2[k] = r_o[2][j];
            joy2[k] = r_o[3][j]; joA[k]  = r_o[4][j];
            jlab[k] = r_lab[j];
        } else {
            jsx1[k]=jsy1[k]=jsx2[k]=jsy2[k]=jsA[k]=0.f;
            jox1[k]=joy1[k]=jox2[k]=joy2[k]=joA[k]=0.f;
            jlab[k] = -1;
        }
    }

    // Build suppression rows; 8 warps stride rows.
    for (int i = wid; i < QQ; i += 8) {
        int   il  = r_lab[i];
        unsigned words[4];
        // cheap label-match pre-ballot per word
        #pragma unroll
        for (int k = 0; k < 4; k++) {
            int j = lane + 32 * k;
            words[k] = __ballot_sync(0xffffffffu, (j > i) && (jlab[k] == il));
        }
        if (words[0] | words[1] | words[2] | words[3]) {
            float ix1 = r_s[0][i], iy1 = r_s[1][i], ix2 = r_s[2][i], iy2 = r_s[3][i], iA = r_s[4][i];
            float px1 = r_o[0][i], py1 = r_o[1][i], px2 = r_o[2][i], py2 = r_o[3][i], pA = r_o[4][i];
            #pragma unroll
            for (int k = 0; k < 4; k++) {
                if (words[k]) {   // warp-uniform: skip IoU math for dead words
                    float w = fmaxf(0.0f, fminf(ix2, jsx2[k]) - fmaxf(ix1, jsx1[k]) + 1.0f);
                    float h = fmaxf(0.0f, fminf(iy2, jsy2[k]) - fmaxf(iy1, jsy1[k]) + 1.0f);
                    float is = w * h;
                    float us = iA + jsA[k] - is;
                    float w2 = fmaxf(0.0f, fminf(px2, jox2[k]) - fmaxf(px1, jox1[k]) + 1.0f);
                    float h2 = fmaxf(0.0f, fminf(py2, joy2[k]) - fmaxf(py1, joy1[k]) + 1.0f);
                    float io = w2 * h2;
                    float uo = pA + joA[k] - io;
                    bool pred = (is * is) * io > 0.49f * (us * us) * uo;
                    words[k] &= __ballot_sync(0xffffffffu, pred);
                }
            }
        }
        if (lane == 0)
            supmat4[i] = make_uint4(words[0], words[1], words[2], words[3]);
    }
    __syncthreads();

    // sequential greedy suppression, software-pipelined row prefetch
    if (tid == 0) {
        unsigned w0 = 0, w1 = 0, w2 = 0, w3 = 0;
        uint4 row = supmat4[0];
        #pragma unroll 4
        for (int i = 0; i < QQ; i++) {
            uint4 next = (i + 1 < QQ) ? supmat4[i + 1] : make_uint4(0,0,0,0);
            unsigned wi = (i < 32) ? w0 : (i < 64) ? w1 : (i < 96) ? w2 : w3;
            if (!((wi >> (i & 31)) & 1u)) {
                w0 |= row.x; w1 |= row.y; w2 |= row.z; w3 |= row.w;
            }
            row = next;
        }
        suppw[0] = w0; suppw[1] = w1; suppw[2] = w2; suppw[3] = w3;
    }
    __syncthreads();

    if (tid < QQ) {
        bool suppressed = (suppw[tid >> 5] >> (tid & 31)) & 1u;
        out[OFF_KEEP + b * QQ + s_orig[tid]] = suppressed ? 0.0f : 1.0f;
    }
}

// ---------------------------------------------------------------------------
extern "C" void kernel_launch(void* const* d_in, const int* in_sizes, int n_in,
                              void* d_out, int out_size)
{
    const float* obj_logits  = (const float*)d_in[0];
    const float* verb_logits = (const float*)d_in[1];
    const float* sub_boxes   = (const float*)d_in[2];
    const float* obj_boxes   = (const float*)d_in[3];
    const float* correct_mat = (const float*)d_in[4];
    const int*   target_sz   = (const int*)d_in[5];
    float* out = (float*)d_out;

    k1_score<<<NQ / 8, 256>>>(obj_logits, verb_logits, sub_boxes, obj_boxes,
                              correct_mat, target_sz, out);
    k2_nms<<<BB, 256>>>(out);
}